// round 6
// baseline (speedup 1.0000x reference)
#include <cuda_runtime.h>
#include <cuda.h>
#include <cuda_bf16.h>
#include <math.h>
#include <stdint.h>

// Problem constants
#define B_   128
#define S_   256
#define D_   1024
#define DH_  64
#define K_   8
#define L_   2
#define NROWS 18          // 16 gathered rows + vmax + vavg
#define MTOT (B_*2*NROWS) // 4608
#define NTOT 256          // q(64)|k(64)|v(64)|mi(64)

// -------- scratch (no allocations allowed) --------
__device__ uint16_t g_Xb[(size_t)MTOT * D_];   // gathered rows + pooled, bf16
__device__ uint16_t g_Wb[(size_t)NTOT * D_];   // packed weights q|k|v|mi, bf16
__device__ float    g_Y [(size_t)MTOT * NTOT]; // projection outputs (f32)

__device__ __forceinline__ uint2 f4_to_bf4(float4 v) {
    __nv_bfloat162 lo = __floats2bfloat162_rn(v.x, v.y);
    __nv_bfloat162 hi = __floats2bfloat162_rn(v.z, v.w);
    uint2 r;
    r.x = *reinterpret_cast<uint32_t*>(&lo);
    r.y = *reinterpret_cast<uint32_t*>(&hi);
    return r;
}

// =====================================================================
// Kernel 1: gather (blocks 0..255, 512 thr: 2 row-halves x 256 cols)
//           + weight pack (blocks 256..287, 512 thr)
// =====================================================================
__global__ void __launch_bounds__(512)
gather_pack_kernel(const float* __restrict__ token,
                   const int* __restrict__ kw_idx,
                   const float* __restrict__ wq, const float* __restrict__ wk,
                   const float* __restrict__ wv, const float* __restrict__ wmi)
{
    int tid = threadIdx.x;
    if (blockIdx.x >= 256) {
        int f4base = (blockIdx.x - 256) * 2048 + tid;
        #pragma unroll
        for (int i = 0; i < 4; i++) {
            int f4 = f4base + i * 512;        // 0..65535
            int wsel = f4 >> 14;              // 16384 float4 per matrix
            const float* W = (wsel == 0) ? wq : (wsel == 1) ? wk :
                             (wsel == 2) ? wv : wmi;
            float4 v = reinterpret_cast<const float4*>(W)[f4 & 16383];
            reinterpret_cast<uint2*>(g_Wb)[f4] = f4_to_bf4(v);
        }
        return;
    }

    __shared__ int idx[K_];
    __shared__ float4 pmax[2][256];
    __shared__ float4 psum[2][256];

    int bs = blockIdx.x;
    int b = bs >> 1, s = bs & 1;
    if (tid < K_)
        idx[tid] = kw_idx[(b * 2 + (1 - s)) * K_ + tid];
    __syncthreads();

    int col = tid & 255;   // float4 column
    int rp  = tid >> 8;    // row half 0..1 (== l)
    const float* tbase = token + (((size_t)b * 2 + s) * L_) * S_ * D_;
    uint16_t* Xrow = g_Xb + (size_t)bs * NROWS * D_;

    float4 mx = make_float4(-3.4e38f, -3.4e38f, -3.4e38f, -3.4e38f);
    float4 sm = make_float4(0.f, 0.f, 0.f, 0.f);

    #pragma unroll
    for (int j = 0; j < 8; j++) {
        int r = rp * 8 + j;
        float4 v = reinterpret_cast<const float4*>(
            tbase + ((size_t)rp * S_ + idx[j]) * D_)[col];
        reinterpret_cast<uint2*>(Xrow + (size_t)r * D_)[col] = f4_to_bf4(v);
        mx.x = fmaxf(mx.x, v.x); mx.y = fmaxf(mx.y, v.y);
        mx.z = fmaxf(mx.z, v.z); mx.w = fmaxf(mx.w, v.w);
        sm.x += v.x; sm.y += v.y; sm.z += v.z; sm.w += v.w;
    }
    pmax[rp][col] = mx;
    psum[rp][col] = sm;
    __syncthreads();

    if (tid < 256) {
        float4 m0 = pmax[0][col], m1 = pmax[1][col];
        float4 s0 = psum[0][col], s1 = psum[1][col];
        float4 M, S;
        M.x = fmaxf(m0.x, m1.x); M.y = fmaxf(m0.y, m1.y);
        M.z = fmaxf(m0.z, m1.z); M.w = fmaxf(m0.w, m1.w);
        S.x = (s0.x + s1.x) * (1.f/16.f);
        S.y = (s0.y + s1.y) * (1.f/16.f);
        S.z = (s0.z + s1.z) * (1.f/16.f);
        S.w = (s0.w + s1.w) * (1.f/16.f);
        reinterpret_cast<uint2*>(Xrow + (size_t)16 * D_)[col] = f4_to_bf4(M);
        reinterpret_cast<uint2*>(Xrow + (size_t)17 * D_)[col] = f4_to_bf4(S);
    }
}

// =====================================================================
// Kernel 2: bf16 tensor GEMM  g_Y[M,256] = X @ W^T
// 64x128x64 block tiles, warp tile 32x32, TMA (SW128) + mbarrier
// 3-stage ring, ldmatrix.x4, mma.m16n8k16.bf16.
// grid (72, 2) = 144 blocks = 1 per SM, single wave.
// =====================================================================
#define A_BYTES (64 * 128)               // 8192 B per stage
#define B_BYTES (128 * 128)              // 16384 B per stage
#define STAGE_BYTES (A_BYTES + B_BYTES)  // 24576
#define GEMM_SMEM (3 * STAGE_BYTES)      // 73728

__device__ __forceinline__ void mbar_wait(uint32_t mbar, int phase) {
    asm volatile(
        "{\n\t.reg .pred P;\n"
        "W%=:\n\t"
        "mbarrier.try_wait.parity.acquire.cta.shared::cta.b64 P, [%0], %1, 0x989680;\n\t"
        "@P bra D%=;\n\t"
        "bra W%=;\n"
        "D%=:\n\t}"
        :: "r"(mbar), "r"(phase) : "memory");
}

__device__ __forceinline__ void tma_2d(uint32_t dst, const CUtensorMap* tm,
                                       int x, int y, uint32_t mbar) {
    asm volatile(
        "cp.async.bulk.tensor.2d.shared::cta.global.tile.mbarrier::complete_tx::bytes "
        "[%0], [%1, {%2, %3}], [%4];"
        :: "r"(dst), "l"(tm), "r"(x), "r"(y), "r"(mbar) : "memory");
}

__global__ void __launch_bounds__(256, 1)
gemm_tc_kernel(const __grid_constant__ CUtensorMap tmA,
               const __grid_constant__ CUtensorMap tmB)
{
    extern __shared__ __align__(1024) uint16_t smem_b[];
    __shared__ __align__(8) uint64_t mbar_s[6];   // full[0..2], empty[0..2]

    const uint32_t smem_s = (uint32_t)__cvta_generic_to_shared(smem_b);
    const uint32_t mb     = (uint32_t)__cvta_generic_to_shared(mbar_s);

    const int tid  = threadIdx.x;
    const int lane = tid & 31;
    const int warp = tid >> 5;
    const int wm   = warp >> 2;     // 0..1  (32 rows each)
    const int wn   = warp & 3;      // 0..3  (32 cols each)
    const int m0   = blockIdx.x * 64;
    const int n0   = blockIdx.y * 128;

    if (tid == 0) {
        #pragma unroll
        for (int s = 0; s < 3; s++) {
            asm volatile("mbarrier.init.shared.b64 [%0], %1;" :: "r"(mb + s * 8), "r"(1) : "memory");
            asm volatile("mbarrier.init.shared.b64 [%0], %1;" :: "r"(mb + 24 + s * 8), "r"(256) : "memory");
        }
    }
    __syncthreads();

    // prologue: fill all 3 stages
    if (tid == 0) {
        #pragma unroll
        for (int s = 0; s < 3; s++) {
            uint32_t fb = mb + s * 8;
            asm volatile("mbarrier.arrive.expect_tx.shared.b64 _, [%0], %1;"
                         :: "r"(fb), "r"(STAGE_BYTES) : "memory");
            uint32_t base = smem_s + s * STAGE_BYTES;
            tma_2d(base,           &tmA, s * 64, m0, fb);
            tma_2d(base + A_BYTES, &tmB, s * 64, n0, fb);
        }
    }

    float c[2][4][4];
    #pragma unroll
    for (int i = 0; i < 2; i++)
        #pragma unroll
        for (int j = 0; j < 4; j++)
            #pragma unroll
            for (int r = 0; r < 4; r++) c[i][j][r] = 0.f;

    // per-lane ldmatrix geometry
    const int j4   = lane >> 3;          // matrix index 0..3
    const int lr   = lane & 7;           // row within 8x8
    const int aRow = wm * 32 + (j4 & 1) * 8 + lr;
    const int aKj  = j4 >> 1;
    const int aSw  = aRow & 7;
    const int bRow = wn * 32 + (j4 >> 1) * 8 + lr;
    const int bKj  = j4 & 1;
    const int bSw  = bRow & 7;
    const uint32_t aByte0 = aRow * 128;
    const uint32_t aByte1 = (aRow + 16) * 128;
    const uint32_t bByte0 = bRow * 128;
    const uint32_t bByte1 = (bRow + 16) * 128;

    int cs = 0, cph = 0;     // consumer stage/phase
    int ps = 0, pep = 0;     // producer empty stage/phase

    for (int kt = 0; kt < 16; kt++) {
        mbar_wait(mb + cs * 8, cph);

        const uint32_t As = smem_s + cs * STAGE_BYTES;
        const uint32_t Bs = As + A_BYTES;

        #pragma unroll
        for (int step = 0; step < 4; step++) {
            const int cA = (2 * step + aKj) ^ aSw;
            const int cB = (2 * step + bKj) ^ bSw;
            uint32_t a0[4], a1[4], b0[4], b1[4];
            {
                uint32_t addr = As + aByte0 + (cA << 4);
                asm volatile("ldmatrix.sync.aligned.m8n8.x4.shared.b16 {%0,%1,%2,%3}, [%4];"
                             : "=r"(a0[0]), "=r"(a0[1]), "=r"(a0[2]), "=r"(a0[3]) : "r"(addr));
            }
            {
                uint32_t addr = As + aByte1 + (cA << 4);
                asm volatile("ldmatrix.sync.aligned.m8n8.x4.shared.b16 {%0,%1,%2,%3}, [%4];"
                             : "=r"(a1[0]), "=r"(a1[1]), "=r"(a1[2]), "=r"(a1[3]) : "r"(addr));
            }
            {
                uint32_t addr = Bs + bByte0 + (cB << 4);
                asm volatile("ldmatrix.sync.aligned.m8n8.x4.shared.b16 {%0,%1,%2,%3}, [%4];"
                             : "=r"(b0[0]), "=r"(b0[1]), "=r"(b0[2]), "=r"(b0[3]) : "r"(addr));
            }
            {
                uint32_t addr = Bs + bByte1 + (cB << 4);
                asm volatile("ldmatrix.sync.aligned.m8n8.x4.shared.b16 {%0,%1,%2,%3}, [%4];"
                             : "=r"(b1[0]), "=r"(b1[1]), "=r"(b1[2]), "=r"(b1[3]) : "r"(addr));
            }
            #pragma unroll
            for (int mt = 0; mt < 2; mt++) {
                const uint32_t* a = mt ? a1 : a0;
                #pragma unroll
                for (int nt = 0; nt < 4; nt++) {
                    const uint32_t* bb = (nt < 2) ? &b0[(nt & 1) * 2] : &b1[(nt & 1) * 2];
                    asm volatile(
                        "mma.sync.aligned.m16n8k16.row.col.f32.bf16.bf16.f32 "
                        "{%0,%1,%2,%3}, {%4,%5,%6,%7}, {%8,%9}, {%0,%1,%2,%3};"
                        : "+f"(c[mt][nt][0]), "+f"(c[mt][nt][1]),
                          "+f"(c[mt][nt][2]), "+f"(c[mt][nt][3])
                        : "r"(a[0]), "r"(a[1]), "r"(a[2]), "r"(a[3]),
                          "r"(bb[0]), "r"(bb[1]));
                }
            }
        }

        // signal stage consumed
        asm volatile("mbarrier.arrive.shared.b64 _, [%0];" :: "r"(mb + 24 + cs * 8) : "memory");

        // refill
        if (tid == 0 && kt + 3 < 16) {
            mbar_wait(mb + 24 + ps * 8, pep);
            uint32_t fb = mb + ps * 8;
            asm volatile("mbarrier.arrive.expect_tx.shared.b64 _, [%0], %1;"
                         :: "r"(fb), "r"(STAGE_BYTES) : "memory");
            uint32_t base = smem_s + ps * STAGE_BYTES;
            tma_2d(base,           &tmA, (kt + 3) * 64, m0, fb);
            tma_2d(base + A_BYTES, &tmB, (kt + 3) * 64, n0, fb);
            ps++; if (ps == 3) { ps = 0; pep ^= 1; }
        }

        cs++; if (cs == 3) { cs = 0; cph ^= 1; }
    }

    // epilogue
    const int g  = lane >> 2;
    const int tg = lane & 3;
    #pragma unroll
    for (int mt = 0; mt < 2; mt++) {
        const int rA = m0 + wm * 32 + mt * 16 + g;
        #pragma unroll
        for (int nt = 0; nt < 4; nt++) {
            const int col = n0 + wn * 32 + nt * 8 + 2 * tg;
            *reinterpret_cast<float2*>(g_Y + (size_t)rA * NTOT + col) =
                make_float2(c[mt][nt][0], c[mt][nt][1]);
            *reinterpret_cast<float2*>(g_Y + (size_t)(rA + 8) * NTOT + col) =
                make_float2(c[mt][nt][2], c[mt][nt][3]);
        }
    }
}

// =====================================================================
// Kernel 3: per-b heads. grid = B blocks, 256 threads.
// =====================================================================
__device__ __forceinline__ float gelu_f(float x) {
    return 0.5f * x * (1.0f + erff(x * 0.70710678118654752440f));
}

__global__ void __launch_bounds__(256)
head_kernel(const float* __restrict__ q_b, const float* __restrict__ k_b,
            const float* __restrict__ v_b, const float* __restrict__ mi_b,
            const float* __restrict__ inter_w, const float* __restrict__ inter_b,
            const float* __restrict__ fc0_w, const float* __restrict__ fc0_b,
            const float* __restrict__ fc1_w, const float* __restrict__ fc1_b,
            float* __restrict__ out)
{
    __shared__ float q0[1024], k0[1024], v0[1024];
    __shared__ float q1[1024], k1[1024], v1[1024];
    __shared__ float att[512];
    __shared__ float e1s[1024], e2s[1024];
    __shared__ float sv[4][64];
    __shared__ float aV[256];
    __shared__ float feat[516];
    __shared__ float h1[64];

    int b = blockIdx.x;
    int tid = threadIdx.x;
    const float* Y0 = g_Y + (size_t)(b * 2 + 0) * NROWS * NTOT;
    const float* Y1 = g_Y + (size_t)(b * 2 + 1) * NROWS * NTOT;

    for (int t = tid; t < 1024; t += 256) {
        int n = t >> 6, h = t & 63;
        q0[t] = Y0[n * NTOT +       h] + q_b[h];
        k0[t] = Y0[n * NTOT +  64 + h] + k_b[h];
        v0[t] = Y0[n * NTOT + 128 + h] + v_b[h];
        q1[t] = Y1[n * NTOT +       h] + q_b[h];
        k1[t] = Y1[n * NTOT +  64 + h] + k_b[h];
        v1[t] = Y1[n * NTOT + 128 + h] + v_b[h];
    }
    if (tid < 64) {
        int h = tid;
        sv[0][h] = Y0[16 * NTOT + 192 + h] + mi_b[h];
        sv[1][h] = Y0[17 * NTOT + 192 + h] + mi_b[h];
        sv[2][h] = Y1[16 * NTOT + 192 + h] + mi_b[h];
        sv[3][h] = Y1[17 * NTOT + 192 + h] + mi_b[h];
    }
    __syncthreads();

    for (int e = tid; e < 512; e += 256) {
        int which = e >> 8, n = (e >> 4) & 15, m = e & 15;
        const float* qq = which ? q1 : q0;
        const float* kk = which ? k0 : k1;
        float s = 0.f;
        #pragma unroll
        for (int h = 0; h < 64; h++) s += qq[n * 64 + h] * kk[m * 64 + h];
        att[e] = s * 0.125f;
    }
    __syncthreads();

    for (int e = tid; e < 2048; e += 256) {
        int which = e >> 10, n = (e >> 6) & 15, h = e & 63;
        const float* vv = which ? v0 : v1;
        float s = 0.f;
        #pragma unroll
        for (int m = 0; m < 16; m++) s += att[which * 256 + n * 16 + m] * vv[m * 64 + h];
        (which ? e2s : e1s)[n * 64 + h] = s;
    }
    __syncthreads();

    if (tid < 128) {
        int which = tid >> 6, hh = tid & 63;
        const float* E = which ? e2s : e1s;
        float mx = -3.4e38f, sm = 0.f;
        #pragma unroll
        for (int n = 0; n < 16; n++) { float v = E[n * 64 + hh]; mx = fmaxf(mx, v); sm += v; }
        feat[which * 128 + hh]      = mx;
        feat[which * 128 + 64 + hh] = sm * (1.f / 16.f);
    }

    {
        int i = tid >> 6, j = tid & 63;
        const float* src = sv[i >> 1];
        float s = inter_b[i * 64 + j];
        const float* wrow = inter_w + ((size_t)i * 64 + j) * 64;
        #pragma unroll
        for (int h = 0; h < 64; h++) s += wrow[h] * src[h];
        aV[i * 64 + j] = s;
    }
    __syncthreads();

    if (tid < 4) {
        int i = tid;
        const float* av = aV + i * 64;
        const float* bvv = sv[2 + (i & 1)];
        float dot = 0.f, na = 0.f, nb = 0.f;
        #pragma unroll
        for (int h = 0; h < 64; h++) {
            dot += av[h] * bvv[h];
            na  += av[h] * av[h];
            nb  += bvv[h] * bvv[h];
        }
        na = fmaxf(sqrtf(na), 1e-8f);
        nb = fmaxf(sqrtf(nb), 1e-8f);
        feat[256 + i] = dot / (na * nb);
    }
    feat[260 + tid] = sv[tid >> 6][tid & 63];
    __syncthreads();

    {
        int j = tid >> 2, part = tid & 3;
        const float* wrow = fc0_w + (size_t)j * 516 + part * 129;
        const float* fr = feat + part * 129;
        float s = 0.f;
        #pragma unroll 4
        for (int i = 0; i < 129; i++) s += fr[i] * wrow[i];
        s += __shfl_xor_sync(0xffffffff, s, 1);
        s += __shfl_xor_sync(0xffffffff, s, 2);
        if (part == 0) h1[j] = gelu_f(fc0_b[j] + s);
    }
    __syncthreads();

    if (tid == 0) {
        float l0 = fc1_b[0], l1 = fc1_b[1];
        #pragma unroll
        for (int j = 0; j < 64; j++) { l0 += h1[j] * fc1_w[j]; l1 += h1[j] * fc1_w[64 + j]; }
        l0 = gelu_f(l0); l1 = gelu_f(l1);
        float m = fmaxf(l0, l1);
        float ea = expf(l0 - m), eb = expf(l1 - m);
        float inv = 1.f / (ea + eb);
        out[b * 2 + 0] = ea * inv;
        out[b * 2 + 1] = eb * inv;
    }
}

// =====================================================================
typedef CUresult (*EncodeTiledFn)(
    CUtensorMap*, CUtensorMapDataType, cuuint32_t, void*,
    const cuuint64_t*, const cuuint64_t*, const cuuint32_t*, const cuuint32_t*,
    CUtensorMapInterleave, CUtensorMapSwizzle, CUtensorMapL2promotion,
    CUtensorMapFloatOOBfill);

extern "C" void kernel_launch(void* const* d_in, const int* in_sizes, int n_in,
                              void* d_out, int out_size)
{
    const float* token   = (const float*)d_in[0];
    const int*   kw_idx  = (const int*)  d_in[1];
    const float* q_w     = (const float*)d_in[2];
    const float* q_b     = (const float*)d_in[3];
    const float* k_w     = (const float*)d_in[4];
    const float* k_b     = (const float*)d_in[5];
    const float* v_w     = (const float*)d_in[6];
    const float* v_b     = (const float*)d_in[7];
    const float* mi_w    = (const float*)d_in[8];
    const float* mi_b    = (const float*)d_in[9];
    const float* inter_w = (const float*)d_in[10];
    const float* inter_b = (const float*)d_in[11];
    const float* fc0_w   = (const float*)d_in[12];
    const float* fc0_b   = (const float*)d_in[13];
    const float* fc1_w   = (const float*)d_in[14];
    const float* fc1_b   = (const float*)d_in[15];
    float* out = (float*)d_out;

    // Build TMA descriptors (host-only work; deterministic each call)
    void* encPtr = nullptr;
    cudaDriverEntryPointQueryResult qr;
    cudaGetDriverEntryPointByVersion("cuTensorMapEncodeTiled", &encPtr, 12000,
                                     cudaEnableDefault, &qr);
    EncodeTiledFn enc = (EncodeTiledFn)encPtr;

    void* xAddr = nullptr;
    void* wAddr = nullptr;
    cudaGetSymbolAddress(&xAddr, g_Xb);
    cudaGetSymbolAddress(&wAddr, g_Wb);

    CUtensorMap tmA, tmB;
    {
        cuuint64_t dims[2]    = {D_, MTOT};
        cuuint64_t strides[1] = {D_ * 2};
        cuuint32_t box[2]     = {64, 64};
        cuuint32_t es[2]      = {1, 1};
        enc(&tmA, CU_TENSOR_MAP_DATA_TYPE_BFLOAT16, 2, xAddr,
            dims, strides, box, es,
            CU_TENSOR_MAP_INTERLEAVE_NONE, CU_TENSOR_MAP_SWIZZLE_128B,
            CU_TENSOR_MAP_L2_PROMOTION_L2_128B, CU_TENSOR_MAP_FLOAT_OOB_FILL_NONE);
    }
    {
        cuuint64_t dims[2]    = {D_, NTOT};
        cuuint64_t strides[1] = {D_ * 2};
        cuuint32_t box[2]     = {64, 128};
        cuuint32_t es[2]      = {1, 1};
        enc(&tmB, CU_TENSOR_MAP_DATA_TYPE_BFLOAT16, 2, wAddr,
            dims, strides, box, es,
            CU_TENSOR_MAP_INTERLEAVE_NONE, CU_TENSOR_MAP_SWIZZLE_128B,
            CU_TENSOR_MAP_L2_PROMOTION_L2_128B, CU_TENSOR_MAP_FLOAT_OOB_FILL_NONE);
    }

    cudaFuncSetAttribute(gemm_tc_kernel,
                         cudaFuncAttributeMaxDynamicSharedMemorySize, GEMM_SMEM);

    gather_pack_kernel<<<256 + 32, 512>>>(token, kw_idx, q_w, k_w, v_w, mi_w);
    gemm_tc_kernel<<<dim3(MTOT / 64, 2), 256, GEMM_SMEM>>>(tmA, tmB);
    head_kernel<<<B_, 256>>>(q_b, k_b, v_b, mi_b, inter_w, inter_b,
                             fc0_w, fc0_b, fc1_w, fc1_b, out);
}